// round 7
// baseline (speedup 1.0000x reference)
#include <cuda_runtime.h>
#include <cuda_fp16.h>

#define N_NODES 100000
#define E_EDGES 1200000
#define F 64

#define SCAN_BLK 256
#define NPART ((N_NODES + SCAN_BLK - 1) / SCAN_BLK)   // 391

// ---------------- scratch (device globals; no allocation allowed) ----------
__device__ int   g_is64;
__device__ int   g_cnt[N_NODES];
__device__ int   g_cur[N_NODES];
__device__ int   g_off[N_NODES + 1];
__device__ int   g_part[NPART];
__device__ int   g_pscan[NPART];
__device__ int   g_srcs[E_EDGES];
__device__ __align__(16) float   g_agg[N_NODES * F];
__device__ __align__(16) float   g_hbuf[2][N_NODES * F];
__device__ __align__(16) __half2 g_h16[3][N_NODES * 32];   // [2] holds x16

// ---------------- dtype detection ------------------------------------------
__global__ void detect_kernel(const int* __restrict__ ei32) {
    __shared__ int any;
    if (threadIdx.x == 0) any = 0;
    __syncthreads();
    int acc = 0;
    for (int i = threadIdx.x * 2 + 1; i < 4096; i += 2 * blockDim.x)
        acc |= ei32[i];
    if (acc) atomicOr(&any, 1);
    __syncthreads();
    if (threadIdx.x == 0) g_is64 = (any == 0) ? 1 : 0;
}

__device__ __forceinline__ int load_idx(const void* ei, long long pos, bool is64) {
    if (is64) return (int)((const long long*)ei)[pos];
    return ((const int*)ei)[pos];
}

// ---------------- x -> fp16 copy --------------------------------------------
__global__ void conv16_kernel(const float* __restrict__ x) {
    int i = blockIdx.x * blockDim.x + threadIdx.x;
    if (i < N_NODES * 32) {
        float2 v = ((const float2*)x)[i];
        g_h16[2][i] = __floats2half2_rn(v.x, v.y);
    }
}

// ---------------- CSR build -------------------------------------------------
__global__ void zero_kernel() {
    int i = blockIdx.x * blockDim.x + threadIdx.x;
    if (i < N_NODES) { g_cnt[i] = 0; g_cur[i] = 0; }
}

__global__ void count_kernel(const void* __restrict__ ei) {
    const bool is64 = (g_is64 != 0);
    int stride = gridDim.x * blockDim.x;
    for (int e = blockIdx.x * blockDim.x + threadIdx.x; e < E_EDGES; e += stride) {
        int d = load_idx(ei, (long long)E_EDGES + e, is64);
        if ((unsigned)d < (unsigned)N_NODES)
            atomicAdd(&g_cnt[d], 1);
    }
}

__global__ void part_sum_kernel() {
    __shared__ int red[SCAN_BLK];
    int i = blockIdx.x * SCAN_BLK + threadIdx.x;
    red[threadIdx.x] = (i < N_NODES) ? g_cnt[i] : 0;
    __syncthreads();
    for (int s = SCAN_BLK / 2; s > 0; s >>= 1) {
        if (threadIdx.x < s) red[threadIdx.x] += red[threadIdx.x + s];
        __syncthreads();
    }
    if (threadIdx.x == 0) g_part[blockIdx.x] = red[0];
}

__global__ void part_scan_kernel() {
    __shared__ int s[512];
    int t = threadIdx.x;
    int v = (t < NPART) ? g_part[t] : 0;
    s[t] = v;
    __syncthreads();
    for (int off = 1; off < 512; off <<= 1) {
        int u = (t >= off) ? s[t - off] : 0;
        __syncthreads();
        s[t] += u;
        __syncthreads();
    }
    if (t < NPART) g_pscan[t] = s[t] - v;
    if (t == 511) g_off[N_NODES] = s[511];
}

__global__ void offsets_kernel() {
    __shared__ int s[SCAN_BLK];
    int t = threadIdx.x;
    int i = blockIdx.x * SCAN_BLK + t;
    int v = (i < N_NODES) ? g_cnt[i] : 0;
    s[t] = v;
    __syncthreads();
    for (int off = 1; off < SCAN_BLK; off <<= 1) {
        int u = (t >= off) ? s[t - off] : 0;
        __syncthreads();
        s[t] += u;
        __syncthreads();
    }
    if (i < N_NODES) g_off[i] = g_pscan[blockIdx.x] + s[t] - v;
}

__global__ void fill_kernel(const void* __restrict__ ei) {
    const bool is64 = (g_is64 != 0);
    int stride = gridDim.x * blockDim.x;
    for (int e = blockIdx.x * blockDim.x + threadIdx.x; e < E_EDGES; e += stride) {
        int d = load_idx(ei, (long long)E_EDGES + e, is64);
        int s = load_idx(ei, (long long)e, is64);
        if ((unsigned)d < (unsigned)N_NODES && (unsigned)s < (unsigned)N_NODES) {
            int p = g_off[d] + atomicAdd(&g_cur[d], 1);
            g_srcs[p] = s;
        }
    }
}

// ---------------- aggregation: one warp per node, fp16 gather ---------------
// Row = 32 half2 = 128B -> ONE L2 line per edge per warp.
__global__ void __launch_bounds__(256)
agg16_kernel(int sel) {
    const __half2* __restrict__ h = g_h16[sel];
    int w = (blockIdx.x * blockDim.x + threadIdx.x) >> 5;
    int lane = threadIdx.x & 31;
    if (w >= N_NODES) return;

    float a0 = 0.f, a1 = 0.f;
    int p = g_off[w], pe = g_off[w + 1];
    for (; p + 4 <= pe; p += 4) {
        int s0 = g_srcs[p], s1 = g_srcs[p + 1], s2 = g_srcs[p + 2], s3 = g_srcs[p + 3];
        float2 f0 = __half22float2(h[(size_t)s0 * 32 + lane]);
        float2 f1 = __half22float2(h[(size_t)s1 * 32 + lane]);
        float2 f2 = __half22float2(h[(size_t)s2 * 32 + lane]);
        float2 f3 = __half22float2(h[(size_t)s3 * 32 + lane]);
        a0 += f0.x + f1.x + f2.x + f3.x;
        a1 += f0.y + f1.y + f2.y + f3.y;
    }
    for (; p < pe; p++) {
        int s0 = g_srcs[p];
        float2 f = __half22float2(h[(size_t)s0 * 32 + lane]);
        a0 += f.x; a1 += f.y;
    }
    // features 2*lane, 2*lane+1 — coalesced 256B float2 store
    ((float2*)(g_agg + (size_t)w * F))[lane] = make_float2(a0, a1);
}

// ---------------- fused dual-GEMM + bias (+tanh), FFMA2 path ----------------
__device__ __forceinline__ float fast_tanh(float x) {
    float e = __expf(2.f * x);
    return 1.f - 2.f / (e + 1.f);
}

#define LIN_THREADS 128
#define TILE_NODES  128
#define ASTRIDE     65
#define WSTRIDE     66
#define LIN_SMEM_FLOATS (2 * 64 * WSTRIDE + 2 * TILE_NODES * ASTRIDE)

__device__ __forceinline__ unsigned long long pack2(float v) {
    unsigned long long r;
    asm("mov.b64 %0, {%1, %1};" : "=l"(r) : "f"(v));
    return r;
}
__device__ __forceinline__ void ffma2(unsigned long long& acc, unsigned long long a,
                                      unsigned long long b) {
    asm("fma.rn.f32x2 %0, %1, %2, %0;" : "+l"(acc) : "l"(a), "l"(b));
}
__device__ __forceinline__ float2 unpack2(unsigned long long v) {
    float lo, hi;
    asm("mov.b64 {%0, %1}, %2;" : "=f"(lo), "=f"(hi) : "l"(v));
    return make_float2(lo, hi);
}

__global__ void __launch_bounds__(LIN_THREADS)
lin_kernel(const float* __restrict__ x, int hin_sel, int hout_sel,
           float* __restrict__ dout, int h16_sel,
           const float* __restrict__ Wl, const float* __restrict__ bl,
           const float* __restrict__ Wr, int do_tanh) {
    extern __shared__ float sm[];
    float* wls = sm;                          // [64][WSTRIDE] k-major
    float* wrs = wls + 64 * WSTRIDE;
    float* as_ = wrs + 64 * WSTRIDE;          // [TILE_NODES][ASTRIDE]
    float* hs_ = as_ + TILE_NODES * ASTRIDE;

    const float* __restrict__ hin = (hin_sel < 0) ? x : g_hbuf[hin_sel];
    float* __restrict__ hout = (hout_sel < 0) ? dout : g_hbuf[hout_sel];

    for (int idx = threadIdx.x; idx < 64 * 64; idx += LIN_THREADS) {
        int f = idx >> 6, k = idx & 63;
        wls[k * WSTRIDE + f] = Wl[idx];
        wrs[k * WSTRIDE + f] = Wr[idx];
    }

    const int base = blockIdx.x * TILE_NODES;
    for (int v = threadIdx.x; v < TILE_NODES * 16; v += LIN_THREADS) {
        int node = v >> 4, kq = (v & 15) * 4;
        int gn = base + node;
        float4 va = make_float4(0.f, 0.f, 0.f, 0.f);
        float4 vh = va;
        if (gn < N_NODES) {
            va = *(const float4*)(g_agg + (size_t)gn * 64 + kq);
            vh = *(const float4*)(hin   + (size_t)gn * 64 + kq);
        }
        float* ap = as_ + node * ASTRIDE + kq;
        ap[0] = va.x; ap[1] = va.y; ap[2] = va.z; ap[3] = va.w;
        float* hp = hs_ + node * ASTRIDE + kq;
        hp[0] = vh.x; hp[1] = vh.y; hp[2] = vh.z; hp[3] = vh.w;
    }
    __syncthreads();

    const int fx = threadIdx.x & 7;
    const int ny = threadIdx.x >> 3;
    const int f0 = fx * 8;
    const int n0 = ny * 8;

    unsigned long long acc[8][4];
    #pragma unroll
    for (int n = 0; n < 8; n++)
        #pragma unroll
        for (int jp = 0; jp < 4; jp++) acc[n][jp] = 0ull;

    #pragma unroll 8
    for (int k = 0; k < 64; k++) {
        const unsigned long long* wl64 =
            (const unsigned long long*)(wls + k * WSTRIDE + f0);
        const unsigned long long* wr64 =
            (const unsigned long long*)(wrs + k * WSTRIDE + f0);
        unsigned long long wl[4], wr[4];
        #pragma unroll
        for (int jp = 0; jp < 4; jp++) { wl[jp] = wl64[jp]; wr[jp] = wr64[jp]; }

        const float* ab = as_ + n0 * ASTRIDE + k;
        const float* hb = hs_ + n0 * ASTRIDE + k;
        #pragma unroll
        for (int n = 0; n < 8; n++) {
            unsigned long long a2 = pack2(ab[n * ASTRIDE]);
            unsigned long long h2 = pack2(hb[n * ASTRIDE]);
            #pragma unroll
            for (int jp = 0; jp < 4; jp++) {
                ffma2(acc[n][jp], a2, wl[jp]);
                ffma2(acc[n][jp], h2, wr[jp]);
            }
        }
    }

    float bias[8];
    #pragma unroll
    for (int j = 0; j < 8; j++) bias[j] = bl[f0 + j];

    #pragma unroll
    for (int n = 0; n < 8; n++) {
        int gn = base + n0 + n;
        if (gn >= N_NODES) continue;
        float v[8];
        #pragma unroll
        for (int jp = 0; jp < 4; jp++) {
            float2 p = unpack2(acc[n][jp]);
            v[2 * jp]     = p.x + bias[2 * jp];
            v[2 * jp + 1] = p.y + bias[2 * jp + 1];
        }
        if (do_tanh) {
            #pragma unroll
            for (int j = 0; j < 8; j++) v[j] = fast_tanh(v[j]);
        }
        float* op = hout + (size_t)gn * 64 + f0;
        *(float4*)(op)     = make_float4(v[0], v[1], v[2], v[3]);
        *(float4*)(op + 4) = make_float4(v[4], v[5], v[6], v[7]);
        if (h16_sel >= 0) {
            __half2 hh[4];
            #pragma unroll
            for (int jp = 0; jp < 4; jp++)
                hh[jp] = __floats2half2_rn(v[2 * jp], v[2 * jp + 1]);
            *(uint4*)(&g_h16[h16_sel][(size_t)gn * 32 + fx * 4]) = *(uint4*)hh;
        }
    }
}

// ---------------- launch -----------------------------------------------------
extern "C" void kernel_launch(void* const* d_in, const int* in_sizes, int n_in,
                              void* d_out, int out_size) {
    const float* x      = (const float*)d_in[0];
    const void*  ei     = d_in[1];
    const float* Wl_in  = (const float*)d_in[2];
    const float* bl_in  = (const float*)d_in[3];
    const float* Wr_in  = (const float*)d_in[4];
    const float* Wl_med = (const float*)d_in[5];
    const float* bl_med = (const float*)d_in[6];
    const float* Wr_med = (const float*)d_in[7];
    const float* Wl_out = (const float*)d_in[8];
    const float* bl_out = (const float*)d_in[9];
    const float* Wr_out = (const float*)d_in[10];
    float*       out    = (float*)d_out;

    static int smem_set = 0;
    const int LIN_SMEM = LIN_SMEM_FLOATS * 4;   // 100,352 bytes
    if (!smem_set) {
        cudaFuncSetAttribute(lin_kernel,
                             cudaFuncAttributeMaxDynamicSharedMemorySize, LIN_SMEM);
        smem_set = 1;
    }

    // CSR build + x fp16 copy
    detect_kernel<<<1, 256>>>((const int*)ei);
    conv16_kernel<<<(N_NODES * 32 + 255) / 256, 256>>>(x);
    zero_kernel<<<(N_NODES + 255) / 256, 256>>>();
    count_kernel<<<1024, 256>>>(ei);
    part_sum_kernel<<<NPART, SCAN_BLK>>>();
    part_scan_kernel<<<1, 512>>>();
    offsets_kernel<<<NPART, SCAN_BLK>>>();
    fill_kernel<<<1024, 256>>>(ei);

    const int AGG_BLOCKS = (N_NODES * 32 + 255) / 256;      // 1 warp / node
    const int LIN_BLOCKS = (N_NODES + TILE_NODES - 1) / TILE_NODES;  // 782

    // layer 0: gather x16 (slot 2); self = x fp32; out -> hbuf0 + h16[0]
    agg16_kernel<<<AGG_BLOCKS, 256>>>(2);
    lin_kernel<<<LIN_BLOCKS, LIN_THREADS, LIN_SMEM>>>(x, -1, 0, nullptr, 0,
                                                      Wl_in, bl_in, Wr_in, 1);
    // layer 1: gather h16[0]; self = hbuf0; out -> hbuf1 + h16[1]
    agg16_kernel<<<AGG_BLOCKS, 256>>>(0);
    lin_kernel<<<LIN_BLOCKS, LIN_THREADS, LIN_SMEM>>>(nullptr, 0, 1, nullptr, 1,
                                                      Wl_med, bl_med, Wr_med, 1);
    // layer 2: gather h16[1]; self = hbuf1; out -> hbuf0 + h16[0]
    agg16_kernel<<<AGG_BLOCKS, 256>>>(1);
    lin_kernel<<<LIN_BLOCKS, LIN_THREADS, LIN_SMEM>>>(nullptr, 1, 0, nullptr, 0,
                                                      Wl_med, bl_med, Wr_med, 1);
    // layer 3: gather h16[0]; self = hbuf0; out -> d_out (fp32, no tanh)
    agg16_kernel<<<AGG_BLOCKS, 256>>>(0);
    lin_kernel<<<LIN_BLOCKS, LIN_THREADS, LIN_SMEM>>>(nullptr, 0, -1, out, -1,
                                                      Wl_out, bl_out, Wr_out, 0);
}

// round 8
// speedup vs baseline: 1.1681x; 1.1681x over previous
#include <cuda_runtime.h>

#define N_NODES 100000
#define E_EDGES 1200000
#define F 64

#define SCAN_BLK 256
#define NPART ((N_NODES + SCAN_BLK - 1) / SCAN_BLK)   // 391

// ---------------- scratch (device globals; no allocation allowed) ----------
__device__ int   g_is64;
__device__ int   g_cnt[N_NODES];
__device__ int   g_cur[N_NODES];
__device__ int   g_off[N_NODES + 1];
__device__ int   g_part[NPART];
__device__ int   g_pscan[NPART];
__device__ int   g_srcs[E_EDGES];
__device__ __align__(16) float g_agg[N_NODES * F];
__device__ __align__(16) float g_hbuf[2][N_NODES * F];

// ---------------- dtype detection ------------------------------------------
__global__ void detect_kernel(const int* __restrict__ ei32) {
    __shared__ int any;
    if (threadIdx.x == 0) any = 0;
    __syncthreads();
    int acc = 0;
    for (int i = threadIdx.x * 2 + 1; i < 4096; i += 2 * blockDim.x)
        acc |= ei32[i];
    if (acc) atomicOr(&any, 1);
    __syncthreads();
    if (threadIdx.x == 0) g_is64 = (any == 0) ? 1 : 0;
}

__device__ __forceinline__ int load_idx(const void* ei, long long pos, bool is64) {
    if (is64) return (int)((const long long*)ei)[pos];
    return ((const int*)ei)[pos];
}

// ---------------- CSR build -------------------------------------------------
__global__ void zero_kernel() {
    int i = blockIdx.x * blockDim.x + threadIdx.x;
    if (i < N_NODES) { g_cnt[i] = 0; g_cur[i] = 0; }
}

__global__ void count_kernel(const void* __restrict__ ei) {
    const bool is64 = (g_is64 != 0);
    int stride = gridDim.x * blockDim.x;
    for (int e = blockIdx.x * blockDim.x + threadIdx.x; e < E_EDGES; e += stride) {
        int d = load_idx(ei, (long long)E_EDGES + e, is64);
        if ((unsigned)d < (unsigned)N_NODES)
            atomicAdd(&g_cnt[d], 1);
    }
}

__global__ void part_sum_kernel() {
    __shared__ int red[SCAN_BLK];
    int i = blockIdx.x * SCAN_BLK + threadIdx.x;
    red[threadIdx.x] = (i < N_NODES) ? g_cnt[i] : 0;
    __syncthreads();
    for (int s = SCAN_BLK / 2; s > 0; s >>= 1) {
        if (threadIdx.x < s) red[threadIdx.x] += red[threadIdx.x + s];
        __syncthreads();
    }
    if (threadIdx.x == 0) g_part[blockIdx.x] = red[0];
}

__global__ void part_scan_kernel() {
    __shared__ int s[512];
    int t = threadIdx.x;
    int v = (t < NPART) ? g_part[t] : 0;
    s[t] = v;
    __syncthreads();
    for (int off = 1; off < 512; off <<= 1) {
        int u = (t >= off) ? s[t - off] : 0;
        __syncthreads();
        s[t] += u;
        __syncthreads();
    }
    if (t < NPART) g_pscan[t] = s[t] - v;
    if (t == 511) g_off[N_NODES] = s[511];
}

__global__ void offsets_kernel() {
    __shared__ int s[SCAN_BLK];
    int t = threadIdx.x;
    int i = blockIdx.x * SCAN_BLK + t;
    int v = (i < N_NODES) ? g_cnt[i] : 0;
    s[t] = v;
    __syncthreads();
    for (int off = 1; off < SCAN_BLK; off <<= 1) {
        int u = (t >= off) ? s[t - off] : 0;
        __syncthreads();
        s[t] += u;
        __syncthreads();
    }
    if (i < N_NODES) g_off[i] = g_pscan[blockIdx.x] + s[t] - v;
}

__global__ void fill_kernel(const void* __restrict__ ei) {
    const bool is64 = (g_is64 != 0);
    int stride = gridDim.x * blockDim.x;
    for (int e = blockIdx.x * blockDim.x + threadIdx.x; e < E_EDGES; e += stride) {
        int d = load_idx(ei, (long long)E_EDGES + e, is64);
        int s = load_idx(ei, (long long)e, is64);
        if ((unsigned)d < (unsigned)N_NODES && (unsigned)s < (unsigned)N_NODES) {
            int p = g_off[d] + atomicAdd(&g_cur[d], 1);
            g_srcs[p] = s;
        }
    }
}

// ---------------- aggregation: one warp per node, edge-pair float4 gather ---
// lanes 0-15 handle even edges, lanes 16-31 odd edges; each lane loads a
// float4 (16 lanes x 16B = full 256B row per edge, 1 LDG.128 per 2 edges).
__global__ void __launch_bounds__(256)
agg_kernel(const float* __restrict__ x, int hin_sel) {
    const float* __restrict__ h = (hin_sel < 0) ? x : g_hbuf[hin_sel];
    int w = (blockIdx.x * blockDim.x + threadIdx.x) >> 5;
    int lane = threadIdx.x & 31;
    if (w >= N_NODES) return;

    const int q = lane & 15;        // float4 slot within row
    const int half = lane >> 4;     // 0: even edges, 1: odd edges

    float ax = 0.f, ay = 0.f, az = 0.f, aw = 0.f;
    int p = g_off[w], pe = g_off[w + 1];
    while (p < pe) {
        int cnt = pe - p; if (cnt > 32) cnt = 32;
        int idx = (lane < cnt) ? g_srcs[p + lane] : 0;   // coalesced index load
        int j = 0;
        for (; j + 4 <= cnt; j += 4) {                   // 4 edges, 2 indep LDG.128
            int s0 = __shfl_sync(0xffffffffu, idx, j + half);
            int s1 = __shfl_sync(0xffffffffu, idx, j + 2 + half);
            float4 v0 = ((const float4*)(h + (size_t)s0 * 64))[q];
            float4 v1 = ((const float4*)(h + (size_t)s1 * 64))[q];
            ax += v0.x + v1.x; ay += v0.y + v1.y;
            az += v0.z + v1.z; aw += v0.w + v1.w;
        }
        for (; j < cnt; j += 2) {                        // remaining 1-3 edges
            int e = j + half;
            int s0 = __shfl_sync(0xffffffffu, idx, e & 31);
            if (e < cnt) {
                float4 v = ((const float4*)(h + (size_t)s0 * 64))[q];
                ax += v.x; ay += v.y; az += v.z; aw += v.w;
            }
        }
        p += cnt;
    }
    // combine even/odd halves
    ax += __shfl_xor_sync(0xffffffffu, ax, 16);
    ay += __shfl_xor_sync(0xffffffffu, ay, 16);
    az += __shfl_xor_sync(0xffffffffu, az, 16);
    aw += __shfl_xor_sync(0xffffffffu, aw, 16);
    if (half == 0)
        ((float4*)(g_agg + (size_t)w * F))[q] = make_float4(ax, ay, az, aw);
}

// ---------------- fused dual-GEMM + bias (+tanh), FFMA2 path ----------------
__device__ __forceinline__ float fast_tanh(float x) {
    float e = __expf(2.f * x);
    return 1.f - 2.f / (e + 1.f);
}

#define LIN_THREADS 128
#define TILE_NODES  128
#define ASTRIDE     65
#define WSTRIDE     66
#define LIN_SMEM_FLOATS (2 * 64 * WSTRIDE + 2 * TILE_NODES * ASTRIDE)

__device__ __forceinline__ unsigned long long pack2(float v) {
    unsigned long long r;
    asm("mov.b64 %0, {%1, %1};" : "=l"(r) : "f"(v));
    return r;
}
__device__ __forceinline__ void ffma2(unsigned long long& acc, unsigned long long a,
                                      unsigned long long b) {
    asm("fma.rn.f32x2 %0, %1, %2, %0;" : "+l"(acc) : "l"(a), "l"(b));
}
__device__ __forceinline__ float2 unpack2(unsigned long long v) {
    float lo, hi;
    asm("mov.b64 {%0, %1}, %2;" : "=f"(lo), "=f"(hi) : "l"(v));
    return make_float2(lo, hi);
}

__global__ void __launch_bounds__(LIN_THREADS)
lin_kernel(const float* __restrict__ x, int hin_sel, int hout_sel,
           float* __restrict__ dout,
           const float* __restrict__ Wl, const float* __restrict__ bl,
           const float* __restrict__ Wr, int do_tanh) {
    extern __shared__ float sm[];
    float* wls = sm;                          // [64][WSTRIDE] k-major
    float* wrs = wls + 64 * WSTRIDE;
    float* as_ = wrs + 64 * WSTRIDE;          // [TILE_NODES][ASTRIDE]
    float* hs_ = as_ + TILE_NODES * ASTRIDE;

    const float* __restrict__ hin = (hin_sel < 0) ? x : g_hbuf[hin_sel];
    float* __restrict__ hout = (hout_sel < 0) ? dout : g_hbuf[hout_sel];

    for (int idx = threadIdx.x; idx < 64 * 64; idx += LIN_THREADS) {
        int f = idx >> 6, k = idx & 63;
        wls[k * WSTRIDE + f] = Wl[idx];
        wrs[k * WSTRIDE + f] = Wr[idx];
    }

    const int base = blockIdx.x * TILE_NODES;
    for (int v = threadIdx.x; v < TILE_NODES * 16; v += LIN_THREADS) {
        int node = v >> 4, kq = (v & 15) * 4;
        int gn = base + node;
        float4 va = make_float4(0.f, 0.f, 0.f, 0.f);
        float4 vh = va;
        if (gn < N_NODES) {
            va = *(const float4*)(g_agg + (size_t)gn * 64 + kq);
            vh = *(const float4*)(hin   + (size_t)gn * 64 + kq);
        }
        float* ap = as_ + node * ASTRIDE + kq;
        ap[0] = va.x; ap[1] = va.y; ap[2] = va.z; ap[3] = va.w;
        float* hp = hs_ + node * ASTRIDE + kq;
        hp[0] = vh.x; hp[1] = vh.y; hp[2] = vh.z; hp[3] = vh.w;
    }
    __syncthreads();

    const int fx = threadIdx.x & 7;
    const int ny = threadIdx.x >> 3;
    const int f0 = fx * 8;
    const int n0 = ny * 8;

    unsigned long long acc[8][4];
    #pragma unroll
    for (int n = 0; n < 8; n++)
        #pragma unroll
        for (int jp = 0; jp < 4; jp++) acc[n][jp] = 0ull;

    #pragma unroll 8
    for (int k = 0; k < 64; k++) {
        const unsigned long long* wl64 =
            (const unsigned long long*)(wls + k * WSTRIDE + f0);
        const unsigned long long* wr64 =
            (const unsigned long long*)(wrs + k * WSTRIDE + f0);
        unsigned long long wl[4], wr[4];
        #pragma unroll
        for (int jp = 0; jp < 4; jp++) { wl[jp] = wl64[jp]; wr[jp] = wr64[jp]; }

        const float* ab = as_ + n0 * ASTRIDE + k;
        const float* hb = hs_ + n0 * ASTRIDE + k;
        #pragma unroll
        for (int n = 0; n < 8; n++) {
            unsigned long long a2 = pack2(ab[n * ASTRIDE]);
            unsigned long long h2 = pack2(hb[n * ASTRIDE]);
            #pragma unroll
            for (int jp = 0; jp < 4; jp++) {
                ffma2(acc[n][jp], a2, wl[jp]);
                ffma2(acc[n][jp], h2, wr[jp]);
            }
        }
    }

    float bias[8];
    #pragma unroll
    for (int j = 0; j < 8; j++) bias[j] = bl[f0 + j];

    #pragma unroll
    for (int n = 0; n < 8; n++) {
        int gn = base + n0 + n;
        if (gn >= N_NODES) continue;
        float v[8];
        #pragma unroll
        for (int jp = 0; jp < 4; jp++) {
            float2 p = unpack2(acc[n][jp]);
            v[2 * jp]     = p.x + bias[2 * jp];
            v[2 * jp + 1] = p.y + bias[2 * jp + 1];
        }
        if (do_tanh) {
            #pragma unroll
            for (int j = 0; j < 8; j++) v[j] = fast_tanh(v[j]);
        }
        float* op = hout + (size_t)gn * 64 + f0;
        *(float4*)(op)     = make_float4(v[0], v[1], v[2], v[3]);
        *(float4*)(op + 4) = make_float4(v[4], v[5], v[6], v[7]);
    }
}

// ---------------- launch -----------------------------------------------------
extern "C" void kernel_launch(void* const* d_in, const int* in_sizes, int n_in,
                              void* d_out, int out_size) {
    const float* x      = (const float*)d_in[0];
    const void*  ei     = d_in[1];
    const float* Wl_in  = (const float*)d_in[2];
    const float* bl_in  = (const float*)d_in[3];
    const float* Wr_in  = (const float*)d_in[4];
    const float* Wl_med = (const float*)d_in[5];
    const float* bl_med = (const float*)d_in[6];
    const float* Wr_med = (const float*)d_in[7];
    const float* Wl_out = (const float*)d_in[8];
    const float* bl_out = (const float*)d_in[9];
    const float* Wr_out = (const float*)d_in[10];
    float*       out    = (float*)d_out;

    static int smem_set = 0;
    const int LIN_SMEM = LIN_SMEM_FLOATS * 4;   // 100,352 bytes
    if (!smem_set) {
        cudaFuncSetAttribute(lin_kernel,
                             cudaFuncAttributeMaxDynamicSharedMemorySize, LIN_SMEM);
        smem_set = 1;
    }

    // CSR build
    detect_kernel<<<1, 256>>>((const int*)ei);
    zero_kernel<<<(N_NODES + 255) / 256, 256>>>();
    count_kernel<<<1024, 256>>>(ei);
    part_sum_kernel<<<NPART, SCAN_BLK>>>();
    part_scan_kernel<<<1, 512>>>();
    offsets_kernel<<<NPART, SCAN_BLK>>>();
    fill_kernel<<<1024, 256>>>(ei);

    const int AGG_BLOCKS = (N_NODES * 32 + 255) / 256;      // 1 warp / node
    const int LIN_BLOCKS = (N_NODES + TILE_NODES - 1) / TILE_NODES;  // 782

    agg_kernel<<<AGG_BLOCKS, 256>>>(x, -1);
    lin_kernel<<<LIN_BLOCKS, LIN_THREADS, LIN_SMEM>>>(x, -1, 0, nullptr,
                                                      Wl_in, bl_in, Wr_in, 1);
    agg_kernel<<<AGG_BLOCKS, 256>>>(nullptr, 0);
    lin_kernel<<<LIN_BLOCKS, LIN_THREADS, LIN_SMEM>>>(nullptr, 0, 1, nullptr,
                                                      Wl_med, bl_med, Wr_med, 1);
    agg_kernel<<<AGG_BLOCKS, 256>>>(nullptr, 1);
    lin_kernel<<<LIN_BLOCKS, LIN_THREADS, LIN_SMEM>>>(nullptr, 1, 0, nullptr,
                                                      Wl_med, bl_med, Wr_med, 1);
    agg_kernel<<<AGG_BLOCKS, 256>>>(nullptr, 0);
    lin_kernel<<<LIN_BLOCKS, LIN_THREADS, LIN_SMEM>>>(nullptr, 0, -1, out,
                                                      Wl_out, bl_out, Wr_out, 0);
}